// round 1
// baseline (speedup 1.0000x reference)
#include <cuda_runtime.h>

#define EPSF 1e-5f

// ---------------- scratch (static device globals; no allocations) ----------
__device__ float g_Y[16 * 256 * 6400];      // 104.9 MB : silu(bn(conv1x1(x)))
__device__ float g_mu[16 * 256];
__device__ float g_rstd[16 * 256];
__device__ float g_attn[16 * 4];
__device__ float g_bias2[16 * 256];         // s1 * (attn @ dy_b) + t1
__device__ float g_w2[16 * 256 * 2304];     // 37.7 MB : s1[o]*rstd[b,i]*agg_w

typedef unsigned long long ull;

__device__ __forceinline__ ull pack_dup(float v) {
    ull r;
    asm("mov.b64 %0, {%1, %2};" : "=l"(r) : "f"(v), "f"(v));
    return r;
}
__device__ __forceinline__ void ffma2(ull &d, ull a, ull b) {
    asm("fma.rn.f32x2 %0, %1, %2, %0;" : "+l"(d) : "l"(a), "l"(b));
}
__device__ __forceinline__ float2 unpack2(ull v) {
    float2 f;
    asm("mov.b64 {%0, %1}, %2;" : "=f"(f.x), "=f"(f.y) : "l"(v));
    return f;
}

// ---------------- K1: 1x1 conv + BN + SiLU -> g_Y --------------------------
// grid (100 px-tiles, 2 o-tiles, 16 b), 256 threads.
// Tile: 128 o x 64 px. Thread: 8 o (4 f32x2 pairs) x 4 px.
__global__ __launch_bounds__(256, 2)
void k1_conv1x1(const float* __restrict__ x, const float* __restrict__ w,
                const float* __restrict__ bg, const float* __restrict__ bb,
                const float* __restrict__ bm, const float* __restrict__ bv)
{
    __shared__ __align__(16) float xs[16 * 64];
    __shared__ __align__(16) float wsT[16 * 130];

    const int b = blockIdx.z, ot = blockIdx.y, pxt = blockIdx.x;
    const int tid = threadIdx.x;
    const int to = tid >> 4, tpx = tid & 15;
    const int obase = ot * 128 + to * 8;
    const int px0 = pxt * 64;

    ull acc[4][4];
#pragma unroll
    for (int a = 0; a < 4; ++a)
#pragma unroll
        for (int p = 0; p < 4; ++p) acc[a][p] = 0ull;

    const float* xb = x + (size_t)b * 128 * 6400;

    for (int c0 = 0; c0 < 128; c0 += 16) {
        __syncthreads();
        {   // xs[cc][px] : coalesced
            int l = tid;
#pragma unroll
            for (int j = 0; j < 4; ++j, l += 256) {
                int cc = l >> 6, px = l & 63;
                xs[cc * 64 + px] = xb[(size_t)(c0 + cc) * 6400 + px0 + px];
            }
        }
        {   // wsT[cc][o] : w is [256,128]
            int l = tid;
#pragma unroll
            for (int j = 0; j < 8; ++j, l += 256) {
                int cc = l & 15, o = l >> 4;
                wsT[cc * 130 + o] = w[(ot * 128 + o) * 128 + c0 + cc];
            }
        }
        __syncthreads();
#pragma unroll
        for (int cc = 0; cc < 16; ++cc) {
            float4 v4 = *reinterpret_cast<const float4*>(&xs[cc * 64 + tpx * 4]);
            ull p0 = pack_dup(v4.x), p1 = pack_dup(v4.y);
            ull p2 = pack_dup(v4.z), p3 = pack_dup(v4.w);
#pragma unroll
            for (int op = 0; op < 4; ++op) {
                ull wp = *reinterpret_cast<const ull*>(&wsT[cc * 130 + to * 8 + 2 * op]);
                ffma2(acc[op][0], wp, p0);
                ffma2(acc[op][1], wp, p1);
                ffma2(acc[op][2], wp, p2);
                ffma2(acc[op][3], wp, p3);
            }
        }
    }
    // epilogue: BN + SiLU
#pragma unroll
    for (int op = 0; op < 4; ++op) {
        int o = obase + 2 * op;
        float s0 = bg[o]     * rsqrtf(bv[o]     + EPSF);
        float s1 = bg[o + 1] * rsqrtf(bv[o + 1] + EPSF);
        float t0 = bb[o]     - bm[o]     * s0;
        float t1 = bb[o + 1] - bm[o + 1] * s1;
        float* y0 = g_Y + ((size_t)b * 256 + o) * 6400 + px0 + tpx * 4;
        float* y1 = y0 + 6400;
#pragma unroll
        for (int p = 0; p < 4; ++p) {
            float2 f = unpack2(acc[op][p]);
            float a0 = f.x * s0 + t0;
            float a1 = f.y * s1 + t1;
            y0[p] = a0 / (1.f + __expf(-a0));
            y1[p] = a1 / (1.f + __expf(-a1));
        }
    }
}

// ---------------- K2: per-(b,c) mean / rstd over 6400 ----------------------
__global__ void k2_stats()
{
    const int bc = blockIdx.x;                  // 0..4095
    const float* p = g_Y + (size_t)bc * 6400;
    float s = 0.f, q = 0.f;
    for (int i = threadIdx.x; i < 6400; i += 256) {
        float v = p[i];
        s += v; q += v * v;
    }
#pragma unroll
    for (int off = 16; off; off >>= 1) {
        s += __shfl_xor_sync(~0u, s, off);
        q += __shfl_xor_sync(~0u, q, off);
    }
    __shared__ float ss[8], qq[8];
    int wrp = threadIdx.x >> 5, lane = threadIdx.x & 31;
    if (lane == 0) { ss[wrp] = s; qq[wrp] = q; }
    __syncthreads();
    if (threadIdx.x == 0) {
        float S = 0.f, Q = 0.f;
#pragma unroll
        for (int i = 0; i < 8; ++i) { S += ss[i]; Q += qq[i]; }
        float mu  = S * (1.f / 6400.f);
        float var = Q * (1.f / 6400.f) - mu * mu;
        g_mu[bc]   = mu;
        g_rstd[bc] = rsqrtf(var + EPSF);
    }
}

// ---------------- K3: attention (fc1-relu-fc2-softmax) + bias2 -------------
// one warp per batch sample
__global__ void k3_attn(const float* __restrict__ fc1w, const float* __restrict__ fc1b,
                        const float* __restrict__ fc2w, const float* __restrict__ fc2b,
                        const float* __restrict__ dyb,
                        const float* __restrict__ b1g, const float* __restrict__ b1b,
                        const float* __restrict__ b1m, const float* __restrict__ b1v)
{
    const int b = blockIdx.x, lane = threadIdx.x;
    const float* mu = g_mu + b * 256;

    float a[4];
#pragma unroll
    for (int k = 0; k < 4; ++k) {
        float s = 0.f;
        for (int c = lane; c < 256; c += 32) s += mu[c] * fc1w[k * 256 + c];
#pragma unroll
        for (int off = 16; off; off >>= 1) s += __shfl_xor_sync(~0u, s, off);
        a[k] = fmaxf(s + fc1b[k], 0.f);
    }
    float z[4], zmax = -1e30f;
#pragma unroll
    for (int j = 0; j < 4; ++j) {
        float s = fc2b[j];
#pragma unroll
        for (int k = 0; k < 4; ++k) s += fc2w[j * 4 + k] * a[k];
        z[j] = s; zmax = fmaxf(zmax, s);
    }
    float den = 0.f;
#pragma unroll
    for (int j = 0; j < 4; ++j) { z[j] = expf(z[j] - zmax); den += z[j]; }
    float attn[4];
#pragma unroll
    for (int j = 0; j < 4; ++j) attn[j] = z[j] / den;
    if (lane == 0) {
#pragma unroll
        for (int j = 0; j < 4; ++j) g_attn[b * 4 + j] = attn[j];
    }
    // bias2 = s1 * (attn @ dy_b) + t1   (bn1 folded)
    for (int o = lane; o < 256; o += 32) {
        float s1 = b1g[o] * rsqrtf(b1v[o] + EPSF);
        float t1 = b1b[o] - b1m[o] * s1;
        float acc = 0.f;
#pragma unroll
        for (int k = 0; k < 4; ++k) acc += attn[k] * dyb[k * 256 + o];
        g_bias2[b * 256 + o] = acc * s1 + t1;
    }
}

// ---------------- K4: aggregate weights, fold rstd and bn1 scale -----------
// g_w2[b][o][i*9+kk] = s1[o] * rstd[b,i] * sum_k attn[b,k] * dy_w[k,o,i,kk]
__global__ void k4_aggw(const float* __restrict__ dyw,
                        const float* __restrict__ b1g, const float* __restrict__ b1v)
{
    const int bo = blockIdx.x;                  // b*256+o
    const int b = bo >> 8, o = bo & 255;
    const float a0 = g_attn[b * 4 + 0], a1 = g_attn[b * 4 + 1];
    const float a2 = g_attn[b * 4 + 2], a3 = g_attn[b * 4 + 3];
    const float s1 = b1g[o] * rsqrtf(b1v[o] + EPSF);
    const float* w0 = dyw + ((size_t)(0 * 256 + o)) * 2304;
    const float* w1 = dyw + ((size_t)(1 * 256 + o)) * 2304;
    const float* w2 = dyw + ((size_t)(2 * 256 + o)) * 2304;
    const float* w3 = dyw + ((size_t)(3 * 256 + o)) * 2304;
    const float* rstd = g_rstd + b * 256;
    float* outp = g_w2 + (size_t)bo * 2304;
    for (int l = threadIdx.x; l < 2304; l += 256) {
        int i = l / 9;
        float v = a0 * w0[l] + a1 * w1[l] + a2 * w2[l] + a3 * w3[l];
        outp[l] = v * s1 * rstd[i];
    }
}

// ---------------- K5: per-sample 3x3 conv (the big one) --------------------
// grid (100 spatial tiles, 2 o-tiles, 16 b), 256 threads.
// Output tile: 128 o x (4h x 16w) px. Thread: 8 o (4 f32x2 pairs) x 4 px (row seg).
// Input staged per 8-channel chunk with (y - mu) applied; rstd/s1 live in g_w2.
__global__ __launch_bounds__(256, 2)
void k5_dyconv(float* __restrict__ out)
{
    __shared__ __align__(16) float ws[72 * 130];     // [m=ikk][o] 37.4 KB
    __shared__ __align__(16) float ins[8 * 6 * 21];  // [ic][rr][cc] 4 KB

    const int b = blockIdx.z, ot = blockIdx.y, st = blockIdx.x;
    const int tx = st % 5, ty = st / 5;
    const int h0 = ty * 4, w0c = tx * 16;
    const int tid = threadIdx.x;
    const int to = tid >> 4, tpx = tid & 15;
    const int r = tpx >> 2, cbase = (tpx & 3) * 4;
    const int obase = ot * 128 + to * 8;

    ull acc[4][4];
#pragma unroll
    for (int a = 0; a < 4; ++a)
#pragma unroll
        for (int p = 0; p < 4; ++p) acc[a][p] = 0ull;

    const float* Yb  = g_Y + (size_t)b * 256 * 6400;
    const float* mub = g_mu + b * 256;
    const float* wgb = g_w2 + ((size_t)(b * 256 + ot * 128)) * 2304;

    for (int ic0 = 0; ic0 < 256; ic0 += 8) {
        __syncthreads();
        {   // weights: [128 o][72 m] -> ws[m*130+o]
            int l = tid;
#pragma unroll
            for (int j = 0; j < 36; ++j, l += 256) {
                int o = l / 72;
                int m = l - o * 72;
                ws[m * 130 + o] = wgb[(size_t)o * 2304 + ic0 * 9 + m];
            }
        }
        // input halo tile: 8ch x 6 x 18, zero-padded, mean-subtracted
        for (int l = tid; l < 864; l += 256) {
            int ic = l / 108;
            int rem = l - ic * 108;
            int rr = rem / 18, cc = rem - rr * 18;
            int gh = h0 + rr - 1, gw = w0c + cc - 1;
            float v = 0.f;
            if ((unsigned)gh < 80u && (unsigned)gw < 80u)
                v = Yb[(size_t)(ic0 + ic) * 6400 + gh * 80 + gw] - mub[ic0 + ic];
            ins[(ic * 6 + rr) * 21 + cc] = v;
        }
        __syncthreads();

#pragma unroll
        for (int i = 0; i < 8; ++i) {
#pragma unroll
            for (int ky = 0; ky < 3; ++ky) {
                const float* row = &ins[(i * 6 + r + ky) * 21 + cbase];
                ull pk[6];
                pk[0] = pack_dup(row[0]); pk[1] = pack_dup(row[1]);
                pk[2] = pack_dup(row[2]); pk[3] = pack_dup(row[3]);
                pk[4] = pack_dup(row[4]); pk[5] = pack_dup(row[5]);
#pragma unroll
                for (int kx = 0; kx < 3; ++kx) {
                    const float* wrow = &ws[(i * 9 + ky * 3 + kx) * 130 + to * 8];
                    ull wp0 = *reinterpret_cast<const ull*>(wrow);
                    ull wp1 = *reinterpret_cast<const ull*>(wrow + 2);
                    ull wp2 = *reinterpret_cast<const ull*>(wrow + 4);
                    ull wp3 = *reinterpret_cast<const ull*>(wrow + 6);
                    ffma2(acc[0][0], wp0, pk[kx + 0]); ffma2(acc[0][1], wp0, pk[kx + 1]);
                    ffma2(acc[0][2], wp0, pk[kx + 2]); ffma2(acc[0][3], wp0, pk[kx + 3]);
                    ffma2(acc[1][0], wp1, pk[kx + 0]); ffma2(acc[1][1], wp1, pk[kx + 1]);
                    ffma2(acc[1][2], wp1, pk[kx + 2]); ffma2(acc[1][3], wp1, pk[kx + 3]);
                    ffma2(acc[2][0], wp2, pk[kx + 0]); ffma2(acc[2][1], wp2, pk[kx + 1]);
                    ffma2(acc[2][2], wp2, pk[kx + 2]); ffma2(acc[2][3], wp2, pk[kx + 3]);
                    ffma2(acc[3][0], wp3, pk[kx + 0]); ffma2(acc[3][1], wp3, pk[kx + 1]);
                    ffma2(acc[3][2], wp3, pk[kx + 2]); ffma2(acc[3][3], wp3, pk[kx + 3]);
                }
            }
        }
    }
    // epilogue: + bias2 (bn1 already folded), write out
#pragma unroll
    for (int op = 0; op < 4; ++op) {
        int o = obase + 2 * op;
        float blo = g_bias2[b * 256 + o];
        float bhi = g_bias2[b * 256 + o + 1];
        float* o0 = out + ((size_t)(b * 256 + o)) * 6400 + (h0 + r) * 80 + w0c + cbase;
        float* o1 = o0 + 6400;
#pragma unroll
        for (int p = 0; p < 4; ++p) {
            float2 f = unpack2(acc[op][p]);
            o0[p] = f.x + blo;
            o1[p] = f.y + bhi;
        }
    }
}

// ---------------- launch ----------------------------------------------------
extern "C" void kernel_launch(void* const* d_in, const int* in_sizes, int n_in,
                              void* d_out, int out_size)
{
    const float* x       = (const float*)d_in[0];
    const float* conv1_w = (const float*)d_in[1];
    const float* bn_g    = (const float*)d_in[2];
    const float* bn_b    = (const float*)d_in[3];
    const float* bn_m    = (const float*)d_in[4];
    const float* bn_v    = (const float*)d_in[5];
    const float* fc1_w   = (const float*)d_in[6];
    const float* fc1_b   = (const float*)d_in[7];
    const float* fc2_w   = (const float*)d_in[8];
    const float* fc2_b   = (const float*)d_in[9];
    const float* dy_w    = (const float*)d_in[10];
    const float* dy_b    = (const float*)d_in[11];
    const float* bn1_g   = (const float*)d_in[12];
    const float* bn1_b   = (const float*)d_in[13];
    const float* bn1_m   = (const float*)d_in[14];
    const float* bn1_v   = (const float*)d_in[15];
    float* out = (float*)d_out;

    k1_conv1x1<<<dim3(100, 2, 16), 256>>>(x, conv1_w, bn_g, bn_b, bn_m, bn_v);
    k2_stats<<<4096, 256>>>();
    k3_attn<<<16, 32>>>(fc1_w, fc1_b, fc2_w, fc2_b, dy_b,
                        bn1_g, bn1_b, bn1_m, bn1_v);
    k4_aggw<<<4096, 256>>>(dy_w, bn1_g, bn1_v);
    k5_dyconv<<<dim3(100, 2, 16), 256>>>(out);
}

// round 2
// speedup vs baseline: 1.0007x; 1.0007x over previous
#include <cuda_runtime.h>

#define EPSF 1e-5f

// ---------------- scratch (static device globals; no allocations) ----------
__device__ float g_Y[16 * 256 * 6400];      // 104.9 MB : silu(bn(conv1x1(x)))
__device__ float g_mu[16 * 256];
__device__ float g_rstd[16 * 256];
__device__ float g_attn[16 * 4];
__device__ float g_bias2[16 * 256];         // s1 * (attn @ dy_b) + t1
__device__ float g_w2[16 * 256 * 2304];     // 37.7 MB : s1[o]*rstd[b,i]*agg_w

typedef unsigned long long ull;

__device__ __forceinline__ ull pack_dup(float v) {
    ull r;
    asm("mov.b64 %0, {%1, %2};" : "=l"(r) : "f"(v), "f"(v));
    return r;
}
__device__ __forceinline__ void ffma2(ull &d, ull a, ull b) {
    asm("fma.rn.f32x2 %0, %1, %2, %0;" : "+l"(d) : "l"(a), "l"(b));
}
__device__ __forceinline__ float2 unpack2(ull v) {
    float2 f;
    asm("mov.b64 {%0, %1}, %2;" : "=f"(f.x), "=f"(f.y) : "l"(v));
    return f;
}

// ---------------- K1: 1x1 conv + BN + SiLU -> g_Y --------------------------
// grid (100 px-tiles, 2 o-tiles, 16 b), 256 threads.
// Tile: 128 o x 64 px. Thread: 8 o (4 f32x2 pairs) x 4 px.
__global__ __launch_bounds__(256, 2)
void k1_conv1x1(const float* __restrict__ x, const float* __restrict__ w,
                const float* __restrict__ bg, const float* __restrict__ bb,
                const float* __restrict__ bm, const float* __restrict__ bv)
{
    __shared__ __align__(16) float xs[16 * 64];
    __shared__ __align__(16) float wsT[16 * 130];

    const int b = blockIdx.z, ot = blockIdx.y, pxt = blockIdx.x;
    const int tid = threadIdx.x;
    const int to = tid >> 4, tpx = tid & 15;
    const int obase = ot * 128 + to * 8;
    const int px0 = pxt * 64;

    ull acc[4][4];
#pragma unroll
    for (int a = 0; a < 4; ++a)
#pragma unroll
        for (int p = 0; p < 4; ++p) acc[a][p] = 0ull;

    const float* xb = x + (size_t)b * 128 * 6400;

    for (int c0 = 0; c0 < 128; c0 += 16) {
        __syncthreads();
        {   // xs[cc][px] : coalesced
            int l = tid;
#pragma unroll
            for (int j = 0; j < 4; ++j, l += 256) {
                int cc = l >> 6, px = l & 63;
                xs[cc * 64 + px] = xb[(size_t)(c0 + cc) * 6400 + px0 + px];
            }
        }
        {   // wsT[cc][o] : w is [256,128]
            int l = tid;
#pragma unroll
            for (int j = 0; j < 8; ++j, l += 256) {
                int cc = l & 15, o = l >> 4;
                wsT[cc * 130 + o] = w[(ot * 128 + o) * 128 + c0 + cc];
            }
        }
        __syncthreads();
#pragma unroll
        for (int cc = 0; cc < 16; ++cc) {
            float4 v4 = *reinterpret_cast<const float4*>(&xs[cc * 64 + tpx * 4]);
            ull p0 = pack_dup(v4.x), p1 = pack_dup(v4.y);
            ull p2 = pack_dup(v4.z), p3 = pack_dup(v4.w);
#pragma unroll
            for (int op = 0; op < 4; ++op) {
                ull wp = *reinterpret_cast<const ull*>(&wsT[cc * 130 + to * 8 + 2 * op]);
                ffma2(acc[op][0], wp, p0);
                ffma2(acc[op][1], wp, p1);
                ffma2(acc[op][2], wp, p2);
                ffma2(acc[op][3], wp, p3);
            }
        }
    }
    // epilogue: BN + SiLU
#pragma unroll
    for (int op = 0; op < 4; ++op) {
        int o = obase + 2 * op;
        float s0 = bg[o]     * rsqrtf(bv[o]     + EPSF);
        float s1 = bg[o + 1] * rsqrtf(bv[o + 1] + EPSF);
        float t0 = bb[o]     - bm[o]     * s0;
        float t1 = bb[o + 1] - bm[o + 1] * s1;
        float* y0 = g_Y + ((size_t)b * 256 + o) * 6400 + px0 + tpx * 4;
        float* y1 = y0 + 6400;
#pragma unroll
        for (int p = 0; p < 4; ++p) {
            float2 f = unpack2(acc[op][p]);
            float a0 = f.x * s0 + t0;
            float a1 = f.y * s1 + t1;
            y0[p] = a0 / (1.f + __expf(-a0));
            y1[p] = a1 / (1.f + __expf(-a1));
        }
    }
}

// ---------------- K2: per-(b,c) mean / rstd over 6400 ----------------------
__global__ void k2_stats()
{
    const int bc = blockIdx.x;                  // 0..4095
    const float* p = g_Y + (size_t)bc * 6400;
    float s = 0.f, q = 0.f;
    for (int i = threadIdx.x; i < 6400; i += 256) {
        float v = p[i];
        s += v; q += v * v;
    }
#pragma unroll
    for (int off = 16; off; off >>= 1) {
        s += __shfl_xor_sync(~0u, s, off);
        q += __shfl_xor_sync(~0u, q, off);
    }
    __shared__ float ss[8], qq[8];
    int wrp = threadIdx.x >> 5, lane = threadIdx.x & 31;
    if (lane == 0) { ss[wrp] = s; qq[wrp] = q; }
    __syncthreads();
    if (threadIdx.x == 0) {
        float S = 0.f, Q = 0.f;
#pragma unroll
        for (int i = 0; i < 8; ++i) { S += ss[i]; Q += qq[i]; }
        float mu  = S * (1.f / 6400.f);
        float var = Q * (1.f / 6400.f) - mu * mu;
        g_mu[bc]   = mu;
        g_rstd[bc] = rsqrtf(var + EPSF);
    }
}

// ---------------- K3: attention (fc1-relu-fc2-softmax) + bias2 -------------
// one warp per batch sample
__global__ void k3_attn(const float* __restrict__ fc1w, const float* __restrict__ fc1b,
                        const float* __restrict__ fc2w, const float* __restrict__ fc2b,
                        const float* __restrict__ dyb,
                        const float* __restrict__ b1g, const float* __restrict__ b1b,
                        const float* __restrict__ b1m, const float* __restrict__ b1v)
{
    const int b = blockIdx.x, lane = threadIdx.x;
    const float* mu = g_mu + b * 256;

    float a[4];
#pragma unroll
    for (int k = 0; k < 4; ++k) {
        float s = 0.f;
        for (int c = lane; c < 256; c += 32) s += mu[c] * fc1w[k * 256 + c];
#pragma unroll
        for (int off = 16; off; off >>= 1) s += __shfl_xor_sync(~0u, s, off);
        a[k] = fmaxf(s + fc1b[k], 0.f);
    }
    float z[4], zmax = -1e30f;
#pragma unroll
    for (int j = 0; j < 4; ++j) {
        float s = fc2b[j];
#pragma unroll
        for (int k = 0; k < 4; ++k) s += fc2w[j * 4 + k] * a[k];
        z[j] = s; zmax = fmaxf(zmax, s);
    }
    float den = 0.f;
#pragma unroll
    for (int j = 0; j < 4; ++j) { z[j] = expf(z[j] - zmax); den += z[j]; }
    float attn[4];
#pragma unroll
    for (int j = 0; j < 4; ++j) attn[j] = z[j] / den;
    if (lane == 0) {
#pragma unroll
        for (int j = 0; j < 4; ++j) g_attn[b * 4 + j] = attn[j];
    }
    // bias2 = s1 * (attn @ dy_b) + t1   (bn1 folded)
    for (int o = lane; o < 256; o += 32) {
        float s1 = b1g[o] * rsqrtf(b1v[o] + EPSF);
        float t1 = b1b[o] - b1m[o] * s1;
        float acc = 0.f;
#pragma unroll
        for (int k = 0; k < 4; ++k) acc += attn[k] * dyb[k * 256 + o];
        g_bias2[b * 256 + o] = acc * s1 + t1;
    }
}

// ---------------- K4: aggregate weights, fold rstd and bn1 scale -----------
// g_w2[b][o][i*9+kk] = s1[o] * rstd[b,i] * sum_k attn[b,k] * dy_w[k,o,i,kk]
__global__ void k4_aggw(const float* __restrict__ dyw,
                        const float* __restrict__ b1g, const float* __restrict__ b1v)
{
    const int bo = blockIdx.x;                  // b*256+o
    const int b = bo >> 8, o = bo & 255;
    const float a0 = g_attn[b * 4 + 0], a1 = g_attn[b * 4 + 1];
    const float a2 = g_attn[b * 4 + 2], a3 = g_attn[b * 4 + 3];
    const float s1 = b1g[o] * rsqrtf(b1v[o] + EPSF);
    const float* w0 = dyw + ((size_t)(0 * 256 + o)) * 2304;
    const float* w1 = dyw + ((size_t)(1 * 256 + o)) * 2304;
    const float* w2 = dyw + ((size_t)(2 * 256 + o)) * 2304;
    const float* w3 = dyw + ((size_t)(3 * 256 + o)) * 2304;
    const float* rstd = g_rstd + b * 256;
    float* outp = g_w2 + (size_t)bo * 2304;
    for (int l = threadIdx.x; l < 2304; l += 256) {
        int i = l / 9;
        float v = a0 * w0[l] + a1 * w1[l] + a2 * w2[l] + a3 * w3[l];
        outp[l] = v * s1 * rstd[i];
    }
}

// ---------------- K5: per-sample 3x3 conv (the big one) --------------------
// grid (100 spatial tiles, 2 o-tiles, 16 b), 256 threads.
// Output tile: 128 o x (4h x 16w) px. Thread: 8 o (4 f32x2 pairs) x 4 px (row seg).
// Input staged per 8-channel chunk with (y - mu) applied; rstd/s1 live in g_w2.
__global__ __launch_bounds__(256, 2)
void k5_dyconv(float* __restrict__ out)
{
    __shared__ __align__(16) float ws[72 * 130];     // [m=ikk][o] 37.4 KB
    __shared__ __align__(16) float ins[8 * 6 * 21];  // [ic][rr][cc] 4 KB

    const int b = blockIdx.z, ot = blockIdx.y, st = blockIdx.x;
    const int tx = st % 5, ty = st / 5;
    const int h0 = ty * 4, w0c = tx * 16;
    const int tid = threadIdx.x;
    const int to = tid >> 4, tpx = tid & 15;
    const int r = tpx >> 2, cbase = (tpx & 3) * 4;
    const int obase = ot * 128 + to * 8;

    ull acc[4][4];
#pragma unroll
    for (int a = 0; a < 4; ++a)
#pragma unroll
        for (int p = 0; p < 4; ++p) acc[a][p] = 0ull;

    const float* Yb  = g_Y + (size_t)b * 256 * 6400;
    const float* mub = g_mu + b * 256;
    const float* wgb = g_w2 + ((size_t)(b * 256 + ot * 128)) * 2304;

    for (int ic0 = 0; ic0 < 256; ic0 += 8) {
        __syncthreads();
        {   // weights: [128 o][72 m] -> ws[m*130+o]
            int l = tid;
#pragma unroll
            for (int j = 0; j < 36; ++j, l += 256) {
                int o = l / 72;
                int m = l - o * 72;
                ws[m * 130 + o] = wgb[(size_t)o * 2304 + ic0 * 9 + m];
            }
        }
        // input halo tile: 8ch x 6 x 18, zero-padded, mean-subtracted
        for (int l = tid; l < 864; l += 256) {
            int ic = l / 108;
            int rem = l - ic * 108;
            int rr = rem / 18, cc = rem - rr * 18;
            int gh = h0 + rr - 1, gw = w0c + cc - 1;
            float v = 0.f;
            if ((unsigned)gh < 80u && (unsigned)gw < 80u)
                v = Yb[(size_t)(ic0 + ic) * 6400 + gh * 80 + gw] - mub[ic0 + ic];
            ins[(ic * 6 + rr) * 21 + cc] = v;
        }
        __syncthreads();

#pragma unroll
        for (int i = 0; i < 8; ++i) {
#pragma unroll
            for (int ky = 0; ky < 3; ++ky) {
                const float* row = &ins[(i * 6 + r + ky) * 21 + cbase];
                ull pk[6];
                pk[0] = pack_dup(row[0]); pk[1] = pack_dup(row[1]);
                pk[2] = pack_dup(row[2]); pk[3] = pack_dup(row[3]);
                pk[4] = pack_dup(row[4]); pk[5] = pack_dup(row[5]);
#pragma unroll
                for (int kx = 0; kx < 3; ++kx) {
                    const float* wrow = &ws[(i * 9 + ky * 3 + kx) * 130 + to * 8];
                    ull wp0 = *reinterpret_cast<const ull*>(wrow);
                    ull wp1 = *reinterpret_cast<const ull*>(wrow + 2);
                    ull wp2 = *reinterpret_cast<const ull*>(wrow + 4);
                    ull wp3 = *reinterpret_cast<const ull*>(wrow + 6);
                    ffma2(acc[0][0], wp0, pk[kx + 0]); ffma2(acc[0][1], wp0, pk[kx + 1]);
                    ffma2(acc[0][2], wp0, pk[kx + 2]); ffma2(acc[0][3], wp0, pk[kx + 3]);
                    ffma2(acc[1][0], wp1, pk[kx + 0]); ffma2(acc[1][1], wp1, pk[kx + 1]);
                    ffma2(acc[1][2], wp1, pk[kx + 2]); ffma2(acc[1][3], wp1, pk[kx + 3]);
                    ffma2(acc[2][0], wp2, pk[kx + 0]); ffma2(acc[2][1], wp2, pk[kx + 1]);
                    ffma2(acc[2][2], wp2, pk[kx + 2]); ffma2(acc[2][3], wp2, pk[kx + 3]);
                    ffma2(acc[3][0], wp3, pk[kx + 0]); ffma2(acc[3][1], wp3, pk[kx + 1]);
                    ffma2(acc[3][2], wp3, pk[kx + 2]); ffma2(acc[3][3], wp3, pk[kx + 3]);
                }
            }
        }
    }
    // epilogue: + bias2 (bn1 already folded), write out
#pragma unroll
    for (int op = 0; op < 4; ++op) {
        int o = obase + 2 * op;
        float blo = g_bias2[b * 256 + o];
        float bhi = g_bias2[b * 256 + o + 1];
        float* o0 = out + ((size_t)(b * 256 + o)) * 6400 + (h0 + r) * 80 + w0c + cbase;
        float* o1 = o0 + 6400;
#pragma unroll
        for (int p = 0; p < 4; ++p) {
            float2 f = unpack2(acc[op][p]);
            o0[p] = f.x + blo;
            o1[p] = f.y + bhi;
        }
    }
}

// ---------------- launch ----------------------------------------------------
extern "C" void kernel_launch(void* const* d_in, const int* in_sizes, int n_in,
                              void* d_out, int out_size)
{
    const float* x       = (const float*)d_in[0];
    const float* conv1_w = (const float*)d_in[1];
    const float* bn_g    = (const float*)d_in[2];
    const float* bn_b    = (const float*)d_in[3];
    const float* bn_m    = (const float*)d_in[4];
    const float* bn_v    = (const float*)d_in[5];
    const float* fc1_w   = (const float*)d_in[6];
    const float* fc1_b   = (const float*)d_in[7];
    const float* fc2_w   = (const float*)d_in[8];
    const float* fc2_b   = (const float*)d_in[9];
    const float* dy_w    = (const float*)d_in[10];
    const float* dy_b    = (const float*)d_in[11];
    const float* bn1_g   = (const float*)d_in[12];
    const float* bn1_b   = (const float*)d_in[13];
    const float* bn1_m   = (const float*)d_in[14];
    const float* bn1_v   = (const float*)d_in[15];
    float* out = (float*)d_out;

    k1_conv1x1<<<dim3(100, 2, 16), 256>>>(x, conv1_w, bn_g, bn_b, bn_m, bn_v);
    k2_stats<<<4096, 256>>>();
    k3_attn<<<16, 32>>>(fc1_w, fc1_b, fc2_w, fc2_b, dy_b,
                        bn1_g, bn1_b, bn1_m, bn1_v);
    k4_aggw<<<4096, 256>>>(dy_w, bn1_g, bn1_v);
    k5_dyconv<<<dim3(100, 2, 16), 256>>>(out);
}

// round 3
// speedup vs baseline: 1.0016x; 1.0009x over previous
#include <cuda_runtime.h>

#define EPSF 1e-5f

// ---------------- scratch (static device globals; no allocations) ----------
__device__ float g_Y[16 * 256 * 6400];      // 104.9 MB : silu(bn(conv1x1(x)))
__device__ float g_mu[16 * 256];
__device__ float g_rstd[16 * 256];
__device__ float g_attn[16 * 4];
__device__ float g_bias2[16 * 256];         // s1 * (attn @ dy_b) + t1
__device__ float g_w2[16 * 256 * 2304];     // 37.7 MB : s1[o]*rstd[b,i]*agg_w

typedef unsigned long long ull;

__device__ __forceinline__ ull pack_dup(float v) {
    ull r;
    asm("mov.b64 %0, {%1, %2};" : "=l"(r) : "f"(v), "f"(v));
    return r;
}
__device__ __forceinline__ void ffma2(ull &d, ull a, ull b) {
    asm("fma.rn.f32x2 %0, %1, %2, %0;" : "+l"(d) : "l"(a), "l"(b));
}
__device__ __forceinline__ float2 unpack2(ull v) {
    float2 f;
    asm("mov.b64 {%0, %1}, %2;" : "=f"(f.x), "=f"(f.y) : "l"(v));
    return f;
}

// ---------------- K1: 1x1 conv + BN + SiLU -> g_Y --------------------------
// grid (100 px-tiles, 2 o-tiles, 16 b), 256 threads.
// Tile: 128 o x 64 px. Thread: 8 o (4 f32x2 pairs) x 4 px.
__global__ __launch_bounds__(256, 2)
void k1_conv1x1(const float* __restrict__ x, const float* __restrict__ w,
                const float* __restrict__ bg, const float* __restrict__ bb,
                const float* __restrict__ bm, const float* __restrict__ bv)
{
    __shared__ __align__(16) float xs[16 * 64];
    __shared__ __align__(16) float wsT[16 * 130];

    const int b = blockIdx.z, ot = blockIdx.y, pxt = blockIdx.x;
    const int tid = threadIdx.x;
    const int to = tid >> 4, tpx = tid & 15;
    const int obase = ot * 128 + to * 8;
    const int px0 = pxt * 64;

    ull acc[4][4];
#pragma unroll
    for (int a = 0; a < 4; ++a)
#pragma unroll
        for (int p = 0; p < 4; ++p) acc[a][p] = 0ull;

    const float* xb = x + (size_t)b * 128 * 6400;

    for (int c0 = 0; c0 < 128; c0 += 16) {
        __syncthreads();
        {   // xs[cc][px] : coalesced
            int l = tid;
#pragma unroll
            for (int j = 0; j < 4; ++j, l += 256) {
                int cc = l >> 6, px = l & 63;
                xs[cc * 64 + px] = xb[(size_t)(c0 + cc) * 6400 + px0 + px];
            }
        }
        {   // wsT[cc][o] : w is [256,128]
            int l = tid;
#pragma unroll
            for (int j = 0; j < 8; ++j, l += 256) {
                int cc = l & 15, o = l >> 4;
                wsT[cc * 130 + o] = w[(ot * 128 + o) * 128 + c0 + cc];
            }
        }
        __syncthreads();
#pragma unroll
        for (int cc = 0; cc < 16; ++cc) {
            float4 v4 = *reinterpret_cast<const float4*>(&xs[cc * 64 + tpx * 4]);
            ull p0 = pack_dup(v4.x), p1 = pack_dup(v4.y);
            ull p2 = pack_dup(v4.z), p3 = pack_dup(v4.w);
#pragma unroll
            for (int op = 0; op < 4; ++op) {
                ull wp = *reinterpret_cast<const ull*>(&wsT[cc * 130 + to * 8 + 2 * op]);
                ffma2(acc[op][0], wp, p0);
                ffma2(acc[op][1], wp, p1);
                ffma2(acc[op][2], wp, p2);
                ffma2(acc[op][3], wp, p3);
            }
        }
    }
    // epilogue: BN + SiLU
#pragma unroll
    for (int op = 0; op < 4; ++op) {
        int o = obase + 2 * op;
        float s0 = bg[o]     * rsqrtf(bv[o]     + EPSF);
        float s1 = bg[o + 1] * rsqrtf(bv[o + 1] + EPSF);
        float t0 = bb[o]     - bm[o]     * s0;
        float t1 = bb[o + 1] - bm[o + 1] * s1;
        float* y0 = g_Y + ((size_t)b * 256 + o) * 6400 + px0 + tpx * 4;
        float* y1 = y0 + 6400;
#pragma unroll
        for (int p = 0; p < 4; ++p) {
            float2 f = unpack2(acc[op][p]);
            float a0 = f.x * s0 + t0;
            float a1 = f.y * s1 + t1;
            y0[p] = a0 / (1.f + __expf(-a0));
            y1[p] = a1 / (1.f + __expf(-a1));
        }
    }
}

// ---------------- K2: per-(b,c) mean / rstd over 6400 ----------------------
__global__ void k2_stats()
{
    const int bc = blockIdx.x;                  // 0..4095
    const float* p = g_Y + (size_t)bc * 6400;
    float s = 0.f, q = 0.f;
    for (int i = threadIdx.x; i < 6400; i += 256) {
        float v = p[i];
        s += v; q += v * v;
    }
#pragma unroll
    for (int off = 16; off; off >>= 1) {
        s += __shfl_xor_sync(~0u, s, off);
        q += __shfl_xor_sync(~0u, q, off);
    }
    __shared__ float ss[8], qq[8];
    int wrp = threadIdx.x >> 5, lane = threadIdx.x & 31;
    if (lane == 0) { ss[wrp] = s; qq[wrp] = q; }
    __syncthreads();
    if (threadIdx.x == 0) {
        float S = 0.f, Q = 0.f;
#pragma unroll
        for (int i = 0; i < 8; ++i) { S += ss[i]; Q += qq[i]; }
        float mu  = S * (1.f / 6400.f);
        float var = Q * (1.f / 6400.f) - mu * mu;
        g_mu[bc]   = mu;
        g_rstd[bc] = rsqrtf(var + EPSF);
    }
}

// ---------------- K3: attention (fc1-relu-fc2-softmax) + bias2 -------------
// one warp per batch sample
__global__ void k3_attn(const float* __restrict__ fc1w, const float* __restrict__ fc1b,
                        const float* __restrict__ fc2w, const float* __restrict__ fc2b,
                        const float* __restrict__ dyb,
                        const float* __restrict__ b1g, const float* __restrict__ b1b,
                        const float* __restrict__ b1m, const float* __restrict__ b1v)
{
    const int b = blockIdx.x, lane = threadIdx.x;
    const float* mu = g_mu + b * 256;

    float a[4];
#pragma unroll
    for (int k = 0; k < 4; ++k) {
        float s = 0.f;
        for (int c = lane; c < 256; c += 32) s += mu[c] * fc1w[k * 256 + c];
#pragma unroll
        for (int off = 16; off; off >>= 1) s += __shfl_xor_sync(~0u, s, off);
        a[k] = fmaxf(s + fc1b[k], 0.f);
    }
    float z[4], zmax = -1e30f;
#pragma unroll
    for (int j = 0; j < 4; ++j) {
        float s = fc2b[j];
#pragma unroll
        for (int k = 0; k < 4; ++k) s += fc2w[j * 4 + k] * a[k];
        z[j] = s; zmax = fmaxf(zmax, s);
    }
    float den = 0.f;
#pragma unroll
    for (int j = 0; j < 4; ++j) { z[j] = expf(z[j] - zmax); den += z[j]; }
    float attn[4];
#pragma unroll
    for (int j = 0; j < 4; ++j) attn[j] = z[j] / den;
    if (lane == 0) {
#pragma unroll
        for (int j = 0; j < 4; ++j) g_attn[b * 4 + j] = attn[j];
    }
    // bias2 = s1 * (attn @ dy_b) + t1   (bn1 folded)
    for (int o = lane; o < 256; o += 32) {
        float s1 = b1g[o] * rsqrtf(b1v[o] + EPSF);
        float t1 = b1b[o] - b1m[o] * s1;
        float acc = 0.f;
#pragma unroll
        for (int k = 0; k < 4; ++k) acc += attn[k] * dyb[k * 256 + o];
        g_bias2[b * 256 + o] = acc * s1 + t1;
    }
}

// ---------------- K4: aggregate weights, fold rstd and bn1 scale -----------
// g_w2[b][o][i*9+kk] = s1[o] * rstd[b,i] * sum_k attn[b,k] * dy_w[k,o,i,kk]
__global__ void k4_aggw(const float* __restrict__ dyw,
                        const float* __restrict__ b1g, const float* __restrict__ b1v)
{
    const int bo = blockIdx.x;                  // b*256+o
    const int b = bo >> 8, o = bo & 255;
    const float a0 = g_attn[b * 4 + 0], a1 = g_attn[b * 4 + 1];
    const float a2 = g_attn[b * 4 + 2], a3 = g_attn[b * 4 + 3];
    const float s1 = b1g[o] * rsqrtf(b1v[o] + EPSF);
    const float* w0 = dyw + ((size_t)(0 * 256 + o)) * 2304;
    const float* w1 = dyw + ((size_t)(1 * 256 + o)) * 2304;
    const float* w2 = dyw + ((size_t)(2 * 256 + o)) * 2304;
    const float* w3 = dyw + ((size_t)(3 * 256 + o)) * 2304;
    const float* rstd = g_rstd + b * 256;
    float* outp = g_w2 + (size_t)bo * 2304;
    for (int l = threadIdx.x; l < 2304; l += 256) {
        int i = l / 9;
        float v = a0 * w0[l] + a1 * w1[l] + a2 * w2[l] + a3 * w3[l];
        outp[l] = v * s1 * rstd[i];
    }
}

// ---------------- K5: per-sample 3x3 conv (the big one) --------------------
// grid (100 spatial tiles, 2 o-tiles, 16 b), 256 threads.
// Output tile: 128 o x (4h x 16w) px. Thread: 8 o (4 f32x2 pairs) x 4 px (row seg).
// Input staged per 8-channel chunk with (y - mu) applied; rstd/s1 live in g_w2.
__global__ __launch_bounds__(256, 2)
void k5_dyconv(float* __restrict__ out)
{
    __shared__ __align__(16) float ws[72 * 130];     // [m=ikk][o] 37.4 KB
    __shared__ __align__(16) float ins[8 * 6 * 21];  // [ic][rr][cc] 4 KB

    const int b = blockIdx.z, ot = blockIdx.y, st = blockIdx.x;
    const int tx = st % 5, ty = st / 5;
    const int h0 = ty * 4, w0c = tx * 16;
    const int tid = threadIdx.x;
    const int to = tid >> 4, tpx = tid & 15;
    const int r = tpx >> 2, cbase = (tpx & 3) * 4;
    const int obase = ot * 128 + to * 8;

    ull acc[4][4];
#pragma unroll
    for (int a = 0; a < 4; ++a)
#pragma unroll
        for (int p = 0; p < 4; ++p) acc[a][p] = 0ull;

    const float* Yb  = g_Y + (size_t)b * 256 * 6400;
    const float* mub = g_mu + b * 256;
    const float* wgb = g_w2 + ((size_t)(b * 256 + ot * 128)) * 2304;

    for (int ic0 = 0; ic0 < 256; ic0 += 8) {
        __syncthreads();
        {   // weights: [128 o][72 m] -> ws[m*130+o]
            int l = tid;
#pragma unroll
            for (int j = 0; j < 36; ++j, l += 256) {
                int o = l / 72;
                int m = l - o * 72;
                ws[m * 130 + o] = wgb[(size_t)o * 2304 + ic0 * 9 + m];
            }
        }
        // input halo tile: 8ch x 6 x 18, zero-padded, mean-subtracted
        for (int l = tid; l < 864; l += 256) {
            int ic = l / 108;
            int rem = l - ic * 108;
            int rr = rem / 18, cc = rem - rr * 18;
            int gh = h0 + rr - 1, gw = w0c + cc - 1;
            float v = 0.f;
            if ((unsigned)gh < 80u && (unsigned)gw < 80u)
                v = Yb[(size_t)(ic0 + ic) * 6400 + gh * 80 + gw] - mub[ic0 + ic];
            ins[(ic * 6 + rr) * 21 + cc] = v;
        }
        __syncthreads();

#pragma unroll
        for (int i = 0; i < 8; ++i) {
#pragma unroll
            for (int ky = 0; ky < 3; ++ky) {
                const float* row = &ins[(i * 6 + r + ky) * 21 + cbase];
                ull pk[6];
                pk[0] = pack_dup(row[0]); pk[1] = pack_dup(row[1]);
                pk[2] = pack_dup(row[2]); pk[3] = pack_dup(row[3]);
                pk[4] = pack_dup(row[4]); pk[5] = pack_dup(row[5]);
#pragma unroll
                for (int kx = 0; kx < 3; ++kx) {
                    const float* wrow = &ws[(i * 9 + ky * 3 + kx) * 130 + to * 8];
                    ull wp0 = *reinterpret_cast<const ull*>(wrow);
                    ull wp1 = *reinterpret_cast<const ull*>(wrow + 2);
                    ull wp2 = *reinterpret_cast<const ull*>(wrow + 4);
                    ull wp3 = *reinterpret_cast<const ull*>(wrow + 6);
                    ffma2(acc[0][0], wp0, pk[kx + 0]); ffma2(acc[0][1], wp0, pk[kx + 1]);
                    ffma2(acc[0][2], wp0, pk[kx + 2]); ffma2(acc[0][3], wp0, pk[kx + 3]);
                    ffma2(acc[1][0], wp1, pk[kx + 0]); ffma2(acc[1][1], wp1, pk[kx + 1]);
                    ffma2(acc[1][2], wp1, pk[kx + 2]); ffma2(acc[1][3], wp1, pk[kx + 3]);
                    ffma2(acc[2][0], wp2, pk[kx + 0]); ffma2(acc[2][1], wp2, pk[kx + 1]);
                    ffma2(acc[2][2], wp2, pk[kx + 2]); ffma2(acc[2][3], wp2, pk[kx + 3]);
                    ffma2(acc[3][0], wp3, pk[kx + 0]); ffma2(acc[3][1], wp3, pk[kx + 1]);
                    ffma2(acc[3][2], wp3, pk[kx + 2]); ffma2(acc[3][3], wp3, pk[kx + 3]);
                }
            }
        }
    }
    // epilogue: + bias2 (bn1 already folded), write out
#pragma unroll
    for (int op = 0; op < 4; ++op) {
        int o = obase + 2 * op;
        float blo = g_bias2[b * 256 + o];
        float bhi = g_bias2[b * 256 + o + 1];
        float* o0 = out + ((size_t)(b * 256 + o)) * 6400 + (h0 + r) * 80 + w0c + cbase;
        float* o1 = o0 + 6400;
#pragma unroll
        for (int p = 0; p < 4; ++p) {
            float2 f = unpack2(acc[op][p]);
            o0[p] = f.x + blo;
            o1[p] = f.y + bhi;
        }
    }
}

// ---------------- launch ----------------------------------------------------
extern "C" void kernel_launch(void* const* d_in, const int* in_sizes, int n_in,
                              void* d_out, int out_size)
{
    const float* x       = (const float*)d_in[0];
    const float* conv1_w = (const float*)d_in[1];
    const float* bn_g    = (const float*)d_in[2];
    const float* bn_b    = (const float*)d_in[3];
    const float* bn_m    = (const float*)d_in[4];
    const float* bn_v    = (const float*)d_in[5];
    const float* fc1_w   = (const float*)d_in[6];
    const float* fc1_b   = (const float*)d_in[7];
    const float* fc2_w   = (const float*)d_in[8];
    const float* fc2_b   = (const float*)d_in[9];
    const float* dy_w    = (const float*)d_in[10];
    const float* dy_b    = (const float*)d_in[11];
    const float* bn1_g   = (const float*)d_in[12];
    const float* bn1_b   = (const float*)d_in[13];
    const float* bn1_m   = (const float*)d_in[14];
    const float* bn1_v   = (const float*)d_in[15];
    float* out = (float*)d_out;

    k1_conv1x1<<<dim3(100, 2, 16), 256>>>(x, conv1_w, bn_g, bn_b, bn_m, bn_v);
    k2_stats<<<4096, 256>>>();
    k3_attn<<<16, 32>>>(fc1_w, fc1_b, fc2_w, fc2_b, dy_b,
                        bn1_g, bn1_b, bn1_m, bn1_v);
    k4_aggw<<<4096, 256>>>(dy_w, bn1_g, bn1_v);
    k5_dyconv<<<dim3(100, 2, 16), 256>>>(out);
}